// round 14
// baseline (speedup 1.0000x reference)
#include <cuda_runtime.h>
#include <cuda_fp16.h>
#include <mma.h>
#include <cstdint>
#include <cstddef>

using namespace nvcuda;

#define HIDDEN 4096
#define INTER  11008
#define MTOT   8192   // B*S

// ---------------- static device scratch ------------------------------------
__device__ __align__(16) __half g_wg[(size_t)INTER * HIDDEN];
__device__ __align__(16) __half g_wu[(size_t)INTER * HIDDEN];
__device__ __align__(16) __half g_wd[(size_t)HIDDEN * INTER];
__device__ __align__(16) __half g_x [(size_t)MTOT  * HIDDEN];
__device__ __align__(16) __half g_h [(size_t)MTOT  * INTER];   // silu(g)*u/16 fp16

// ---------------- conversion kernels ---------------------------------------
__global__ void k_i32_to_h(const int* __restrict__ in, __half* __restrict__ out, int n8) {
    int i = blockIdx.x * blockDim.x + threadIdx.x;
    if (i >= n8) return;
    int4 a = reinterpret_cast<const int4*>(in)[2 * i];
    int4 b = reinterpret_cast<const int4*>(in)[2 * i + 1];
    union { __half h[8]; float4 f; } O;
    O.h[0] = __int2half_rn(a.x); O.h[1] = __int2half_rn(a.y);
    O.h[2] = __int2half_rn(a.z); O.h[3] = __int2half_rn(a.w);
    O.h[4] = __int2half_rn(b.x); O.h[5] = __int2half_rn(b.y);
    O.h[6] = __int2half_rn(b.z); O.h[7] = __int2half_rn(b.w);
    reinterpret_cast<float4*>(out)[i] = O.f;
}

__global__ void k_f32_to_h(const float* __restrict__ in, __half* __restrict__ out, int n8) {
    int i = blockIdx.x * blockDim.x + threadIdx.x;
    if (i >= n8) return;
    float4 a = reinterpret_cast<const float4*>(in)[2 * i];
    float4 b = reinterpret_cast<const float4*>(in)[2 * i + 1];
    union { __half h[8]; float4 f; } O;
    O.h[0] = __float2half(a.x); O.h[1] = __float2half(a.y);
    O.h[2] = __float2half(a.z); O.h[3] = __float2half(a.w);
    O.h[4] = __float2half(b.x); O.h[5] = __float2half(b.y);
    O.h[6] = __float2half(b.z); O.h[7] = __float2half(b.w);
    reinterpret_cast<float4*>(out)[i] = O.f;
}

// ---------------- helpers ---------------------------------------------------
__device__ __forceinline__ void cp_async16(void* sdst, const void* gsrc) {
    uint32_t s = (uint32_t)__cvta_generic_to_shared(sdst);
    asm volatile("cp.async.cg.shared.global [%0], [%1], 16;\n" :: "r"(s), "l"(gsrc));
}
__device__ __forceinline__ void cp_commit() { asm volatile("cp.async.commit_group;\n"); }
__device__ __forceinline__ void cp_wait2()  { asm volatile("cp.async.wait_group 2;\n"); }

__device__ __forceinline__ void tile_map(int bid, int nTiles, int GM, int& m, int& n) {
    int per_panel = GM * nTiles;
    int panel = bid / per_panel;
    int rem   = bid - panel * per_panel;
    n = rem / GM;
    m = panel * GM + (rem - n * GM);
}

// Stage geometry (pitch 72 halves = 144 B, LDSM conflict-free)
#define P1    72
#define S1_H  ((128 + 128 + 128) * P1)   // gemm1 stage halves -> 55,296 B
#define S2_H  ((128 + 128) * P1)         // gemm2 stage halves -> 36,864 B
#define G1_SMEM (4 * S1_H * 2)           // 221,184 B (1 CTA/SM)
#define G2_SMEM (4 * S2_H * 2)           // 147,456 B

// ---------------- GEMM1: gate+up fused, CTA 128x128, 16 warps 32x32 ---------
__global__ __launch_bounds__(512, 1)
void k_gemm_swiglu(const float* __restrict__ s_gate, const float* __restrict__ s_up) {
    extern __shared__ __half sm[];

    const int tid = threadIdx.x;
    const int wid = tid >> 5;
    const int wm  = wid >> 2;          // 0..3 (32-row slabs)
    const int wn  = wid & 3;           // 0..3 (32-col slabs)

    int mTile, nTile;
    tile_map(blockIdx.x, INTER / 128, 16, mTile, nTile);
    const int mBase = mTile * 128;
    const int nBase = nTile * 128;

    wmma::fragment<wmma::accumulator, 16, 16, 16, float> accg[2][2], accu[2][2];
#pragma unroll
    for (int i = 0; i < 2; i++)
#pragma unroll
        for (int j = 0; j < 2; j++) { wmma::fill_fragment(accg[i][j], 0.0f); wmma::fill_fragment(accu[i][j], 0.0f); }

    const __half* gA  = g_x  + (size_t)mBase * HIDDEN;
    const __half* gBg = g_wg + (size_t)nBase * HIDDEN;
    const __half* gBu = g_wu + (size_t)nBase * HIDDEN;

    const int r8 = tid >> 3, c8 = tid & 7;   // 64 rows x 8 chunks per pass

    auto prefetch = [&](int kt, int s) {
        __half* sA  = sm + s * S1_H;
        __half* sBg = sA + 128 * P1;
        __half* sBu = sBg + 128 * P1;
        const int kc = kt * 64;
#pragma unroll
        for (int j = 0; j < 2; j++) {            // A: 1024 chunks / 512 thr
            int r = r8 + j * 64;
            cp_async16(sA + r * P1 + c8 * 8, gA + (size_t)r * HIDDEN + kc + c8 * 8);
        }
#pragma unroll
        for (int j = 0; j < 2; j++) {            // Bg/Bu: 1024 chunks each
            int r = r8 + j * 64;
            cp_async16(sBg + r * P1 + c8 * 8, gBg + (size_t)r * HIDDEN + kc + c8 * 8);
            cp_async16(sBu + r * P1 + c8 * 8, gBu + (size_t)r * HIDDEN + kc + c8 * 8);
        }
        cp_commit();
    };

    const int NK = HIDDEN / 64;  // 64
    prefetch(0, 0); prefetch(1, 1); prefetch(2, 2);

    for (int kt = 0; kt < NK; kt++) {
        const int s = kt & 3;
        cp_wait2();            // oldest outstanding group (stage s) complete
        __syncthreads();       // stage s visible; all warps finished kt-1
        if (kt + 3 < NK) prefetch(kt + 3, (kt + 3) & 3);

        const __half* sA  = sm + s * S1_H;
        const __half* sBg = sA + 128 * P1;
        const __half* sBu = sBg + 128 * P1;

#pragma unroll
        for (int ks = 0; ks < 64; ks += 16) {
            wmma::fragment<wmma::matrix_a, 16, 16, 16, __half, wmma::row_major> af[2];
#pragma unroll
            for (int mt = 0; mt < 2; mt++)
                wmma::load_matrix_sync(af[mt], sA + (wm * 32 + mt * 16) * P1 + ks, P1);
#pragma unroll
            for (int nt = 0; nt < 2; nt++) {
                wmma::fragment<wmma::matrix_b, 16, 16, 16, __half, wmma::col_major> bg, bu;
                wmma::load_matrix_sync(bg, sBg + (wn * 32 + nt * 16) * P1 + ks, P1);
                wmma::load_matrix_sync(bu, sBu + (wn * 32 + nt * 16) * P1 + ks, P1);
#pragma unroll
                for (int mt = 0; mt < 2; mt++) {
                    wmma::mma_sync(accg[mt][nt], af[mt], bg, accg[mt][nt]);
                    wmma::mma_sync(accu[mt][nt], af[mt], bu, accu[mt][nt]);
                }
            }
        }
    }

    // ---- fused SwiGLU epilogue via smem staging
    __syncthreads();
    float* sG = reinterpret_cast<float*>(sm);        // 128 x 132
    float* sU = sG + 128 * 132;                      // 128 x 132
#pragma unroll
    for (int mt = 0; mt < 2; mt++)
#pragma unroll
        for (int nt = 0; nt < 2; nt++) {
            int r0 = wm * 32 + mt * 16, c0 = wn * 32 + nt * 16;
            wmma::store_matrix_sync(sG + r0 * 132 + c0, accg[mt][nt], 132, wmma::mem_row_major);
            wmma::store_matrix_sync(sU + r0 * 132 + c0, accu[mt][nt], 132, wmma::mem_row_major);
        }
    __syncthreads();

#pragma unroll
    for (int j = 0; j < 8; j++) {
        int idx = tid + j * 512;          // 128 x 32 float4 groups
        int r = idx >> 5, cc = idx & 31;
        float4 g = *reinterpret_cast<const float4*>(sG + r * 132 + cc * 4);
        float4 u = *reinterpret_cast<const float4*>(sU + r * 132 + cc * 4);
        int c0 = nBase + cc * 4;
        float g0 = g.x * s_gate[c0],     u0 = u.x * s_up[c0];
        float g1 = g.y * s_gate[c0 + 1], u1 = u.y * s_up[c0 + 1];
        float g2 = g.z * s_gate[c0 + 2], u2 = u.z * s_up[c0 + 2];
        float g3 = g.w * s_gate[c0 + 3], u3 = u.w * s_up[c0 + 3];
        float h0 = (g0 / (1.f + __expf(-g0))) * u0 * 0.0625f;
        float h1 = (g1 / (1.f + __expf(-g1))) * u1 * 0.0625f;
        float h2 = (g2 / (1.f + __expf(-g2))) * u2 * 0.0625f;
        float h3 = (g3 / (1.f + __expf(-g3))) * u3 * 0.0625f;
        union { __half h[4]; uint2 v; } O;
        O.h[0] = __float2half(h0); O.h[1] = __float2half(h1);
        O.h[2] = __float2half(h2); O.h[3] = __float2half(h3);
        *reinterpret_cast<uint2*>(&g_h[(size_t)(mBase + r) * INTER + c0]) = O.v;
    }
}

// ---------------- GEMM2: down proj, CTA 128x128, 16 warps 32x32 -------------
__global__ __launch_bounds__(512, 1)
void k_gemm_down(const float* __restrict__ s_down, float* __restrict__ out) {
    extern __shared__ __half sm2[];

    const int tid = threadIdx.x;
    const int wid = tid >> 5;
    const int wm  = wid >> 2;
    const int wn  = wid & 3;

    int mTile, nTile;
    tile_map(blockIdx.x, HIDDEN / 128, 16, mTile, nTile);
    const int mBase = mTile * 128;
    const int nBase = nTile * 128;

    wmma::fragment<wmma::accumulator, 16, 16, 16, float> acc[2][2];
#pragma unroll
    for (int i = 0; i < 2; i++)
#pragma unroll
        for (int j = 0; j < 2; j++) wmma::fill_fragment(acc[i][j], 0.0f);

    const __half* gA = g_h  + (size_t)mBase * INTER;
    const __half* gB = g_wd + (size_t)nBase * INTER;

    const int r8 = tid >> 3, c8 = tid & 7;

    auto prefetch = [&](int kt, int s) {
        __half* sA = sm2 + s * S2_H;
        __half* sB = sA + 128 * P1;
        const int kc = kt * 64;
#pragma unroll
        for (int j = 0; j < 2; j++) {
            int r = r8 + j * 64;
            cp_async16(sA + r * P1 + c8 * 8, gA + (size_t)r * INTER + kc + c8 * 8);
            cp_async16(sB + r * P1 + c8 * 8, gB + (size_t)r * INTER + kc + c8 * 8);
        }
        cp_commit();
    };

    const int NK = INTER / 64;   // 172
    prefetch(0, 0); prefetch(1, 1); prefetch(2, 2);

    for (int kt = 0; kt < NK; kt++) {
        const int s = kt & 3;
        cp_wait2();
        __syncthreads();
        if (kt + 3 < NK) prefetch(kt + 3, (kt + 3) & 3);

        const __half* sA = sm2 + s * S2_H;
        const __half* sB = sA + 128 * P1;

#pragma unroll
        for (int ks = 0; ks < 64; ks += 16) {
            wmma::fragment<wmma::matrix_a, 16, 16, 16, __half, wmma::row_major> af[2];
#pragma unroll
            for (int mt = 0; mt < 2; mt++)
                wmma::load_matrix_sync(af[mt], sA + (wm * 32 + mt * 16) * P1 + ks, P1);
#pragma unroll
            for (int nt = 0; nt < 2; nt++) {
                wmma::fragment<wmma::matrix_b, 16, 16, 16, __half, wmma::col_major> bf;
                wmma::load_matrix_sync(bf, sB + (wn * 32 + nt * 16) * P1 + ks, P1);
#pragma unroll
                for (int mt = 0; mt < 2; mt++)
                    wmma::mma_sync(acc[mt][nt], af[mt], bf, acc[mt][nt]);
            }
        }
    }

    // ---- fused scale epilogue via smem staging
    __syncthreads();
    float* sO = reinterpret_cast<float*>(sm2);       // 128 x 132
#pragma unroll
    for (int mt = 0; mt < 2; mt++)
#pragma unroll
        for (int nt = 0; nt < 2; nt++) {
            int r0 = wm * 32 + mt * 16, c0 = wn * 32 + nt * 16;
            wmma::store_matrix_sync(sO + r0 * 132 + c0, acc[mt][nt], 132, wmma::mem_row_major);
        }
    __syncthreads();

#pragma unroll
    for (int j = 0; j < 8; j++) {
        int idx = tid + j * 512;
        int r = idx >> 5, cc = idx & 31;
        float4 v = *reinterpret_cast<const float4*>(sO + r * 132 + cc * 4);
        int c0 = nBase + cc * 4;
        float4 o;
        o.x = v.x * s_down[c0]     * 16.f;
        o.y = v.y * s_down[c0 + 1] * 16.f;
        o.z = v.z * s_down[c0 + 2] * 16.f;
        o.w = v.w * s_down[c0 + 3] * 16.f;
        *reinterpret_cast<float4*>(&out[(size_t)(mBase + r) * HIDDEN + c0]) = o;
    }
}

// ---------------- launch -----------------------------------------------------
// Inputs by element count (dict order, x first). Weights are int32 (upcast int8).
extern "C" void kernel_launch(void* const* d_in, const int* in_sizes, int n_in,
                              void* d_out, int out_size) {
    int ix = -1, isd = -1;
    int is_[2]; int ns = 0;
    int iw_[3]; int nw = 0;
    for (int i = 0; i < n_in; i++) {
        int sz = in_sizes[i];
        if (sz == MTOT * HIDDEN)       ix = i;
        else if (sz == HIDDEN)         isd = i;
        else if (sz == INTER)          { if (ns < 2) is_[ns++] = i; }
        else if (sz == INTER * HIDDEN) { if (nw < 3) iw_[nw++] = i; }
    }
    bool dict_order = (ix == 0);
    int iwg = dict_order ? iw_[0] : iw_[1];
    int iwu = dict_order ? iw_[1] : iw_[2];
    int iwd = dict_order ? iw_[2] : iw_[0];

    const float* x  = (const float*)d_in[ix];
    const int*   wg = (const int*)  d_in[iwg];
    const float* sg = (const float*)d_in[is_[0]];
    const int*   wu = (const int*)  d_in[iwu];
    const float* su = (const float*)d_in[is_[1]];
    const int*   wd = (const int*)  d_in[iwd];
    const float* sd = (const float*)d_in[isd];
    float* out = (float*)d_out;

    void *pwg, *pwu, *pwd, *px;
    cudaGetSymbolAddress(&pwg, g_wg);
    cudaGetSymbolAddress(&pwu, g_wu);
    cudaGetSymbolAddress(&pwd, g_wd);
    cudaGetSymbolAddress(&px,  g_x);

    static bool attr_done = false;
    if (!attr_done) {
        cudaFuncSetAttribute(k_gemm_swiglu, cudaFuncAttributeMaxDynamicSharedMemorySize, G1_SMEM);
        cudaFuncSetAttribute(k_gemm_down,   cudaFuncAttributeMaxDynamicSharedMemorySize, G2_SMEM);
        attr_done = true;
    }

    const int nW8 = (INTER * HIDDEN) / 8;
    const int nX8 = (MTOT * HIDDEN) / 8;
    k_i32_to_h<<<(nW8 + 255) / 256, 256>>>(wg, (__half*)pwg, nW8);
    k_i32_to_h<<<(nW8 + 255) / 256, 256>>>(wu, (__half*)pwu, nW8);
    k_i32_to_h<<<(nW8 + 255) / 256, 256>>>(wd, (__half*)pwd, nW8);
    k_f32_to_h<<<(nX8 + 255) / 256, 256>>>(x, (__half*)px, nX8);

    k_gemm_swiglu<<<(MTOT / 128) * (INTER / 128), 512, G1_SMEM>>>(sg, su);
    k_gemm_down  <<<(MTOT / 128) * (HIDDEN / 128), 512, G2_SMEM>>>(sd, out);
}

// round 15
// speedup vs baseline: 1.2144x; 1.2144x over previous
#include <cuda_runtime.h>
#include <cuda_fp16.h>
#include <mma.h>
#include <cstdint>
#include <cstddef>

using namespace nvcuda;

#define HIDDEN 4096
#define INTER  11008
#define MTOT   8192   // B*S

// ---------------- static device scratch ------------------------------------
__device__ __align__(16) __half g_wg[(size_t)INTER * HIDDEN];
__device__ __align__(16) __half g_wu[(size_t)INTER * HIDDEN];
__device__ __align__(16) __half g_wd[(size_t)HIDDEN * INTER];
__device__ __align__(16) __half g_x [(size_t)MTOT  * HIDDEN];
__device__ __align__(16) __half g_h [(size_t)MTOT  * INTER];   // silu(g)*u/16 fp16

// ---------------- conversion kernels ---------------------------------------
__global__ void k_i32_to_h(const int* __restrict__ in, __half* __restrict__ out, int n8) {
    int i = blockIdx.x * blockDim.x + threadIdx.x;
    if (i >= n8) return;
    int4 a = reinterpret_cast<const int4*>(in)[2 * i];
    int4 b = reinterpret_cast<const int4*>(in)[2 * i + 1];
    union { __half h[8]; float4 f; } O;
    O.h[0] = __int2half_rn(a.x); O.h[1] = __int2half_rn(a.y);
    O.h[2] = __int2half_rn(a.z); O.h[3] = __int2half_rn(a.w);
    O.h[4] = __int2half_rn(b.x); O.h[5] = __int2half_rn(b.y);
    O.h[6] = __int2half_rn(b.z); O.h[7] = __int2half_rn(b.w);
    reinterpret_cast<float4*>(out)[i] = O.f;
}

__global__ void k_f32_to_h(const float* __restrict__ in, __half* __restrict__ out, int n8) {
    int i = blockIdx.x * blockDim.x + threadIdx.x;
    if (i >= n8) return;
    float4 a = reinterpret_cast<const float4*>(in)[2 * i];
    float4 b = reinterpret_cast<const float4*>(in)[2 * i + 1];
    union { __half h[8]; float4 f; } O;
    O.h[0] = __float2half(a.x); O.h[1] = __float2half(a.y);
    O.h[2] = __float2half(a.z); O.h[3] = __float2half(a.w);
    O.h[4] = __float2half(b.x); O.h[5] = __float2half(b.y);
    O.h[6] = __float2half(b.z); O.h[7] = __float2half(b.w);
    reinterpret_cast<float4*>(out)[i] = O.f;
}

// ---------------- helpers ---------------------------------------------------
__device__ __forceinline__ void cp_async16(void* sdst, const void* gsrc) {
    uint32_t s = (uint32_t)__cvta_generic_to_shared(sdst);
    asm volatile("cp.async.cg.shared.global [%0], [%1], 16;\n" :: "r"(s), "l"(gsrc));
}
__device__ __forceinline__ void cp_commit() { asm volatile("cp.async.commit_group;\n"); }
__device__ __forceinline__ void cp_wait1()  { asm volatile("cp.async.wait_group 1;\n"); }

__device__ __forceinline__ void tile_map(int bid, int nTiles, int GM, int& m, int& n) {
    int per_panel = GM * nTiles;
    int panel = bid / per_panel;
    int rem   = bid - panel * per_panel;
    n = rem / GM;
    m = panel * GM + (rem - n * GM);
}

// Stage geometry (pitch 72 halves = 144 B, LDSM conflict-free)
#define P1    72
#define S1_H  ((128 + 64 + 64) * P1)   // gemm1 stage halves -> 36,864 B
#define S2_H  ((128 + 128) * P1)       // gemm2 stage halves -> 36,864 B
#define G1_SMEM (3 * S1_H * 2)         // 110,592 B (x2 CTAs = 221 KB)
#define G2_SMEM (3 * S2_H * 2)         // 110,592 B (x2 CTAs = 221 KB)

// ---------------- GEMM1: gate+up fused, CTA 128x64, 8 warps 32x32, 3 stages -
// (unchanged from R12 champion)
__global__ __launch_bounds__(256, 2)
void k_gemm_swiglu(const float* __restrict__ s_gate, const float* __restrict__ s_up) {
    extern __shared__ __half sm[];

    const int tid = threadIdx.x;
    const int wid = tid >> 5;
    const int wm  = wid >> 1, wn = wid & 1;

    int mTile, nTile;
    tile_map(blockIdx.x, INTER / 64, 16, mTile, nTile);
    const int mBase = mTile * 128;
    const int nBase = nTile * 64;

    wmma::fragment<wmma::accumulator, 16, 16, 16, float> accg[2][2], accu[2][2];
#pragma unroll
    for (int i = 0; i < 2; i++)
#pragma unroll
        for (int j = 0; j < 2; j++) { wmma::fill_fragment(accg[i][j], 0.0f); wmma::fill_fragment(accu[i][j], 0.0f); }

    const __half* gA  = g_x  + (size_t)mBase * HIDDEN;
    const __half* gBg = g_wg + (size_t)nBase * HIDDEN;
    const __half* gBu = g_wu + (size_t)nBase * HIDDEN;

    const int r8 = tid >> 3, c8 = tid & 7;

    auto prefetch = [&](int kt, int s) {
        __half* sA  = sm + s * S1_H;
        __half* sBg = sA + 128 * P1;
        __half* sBu = sBg + 64 * P1;
        const int kc = kt * 64;
#pragma unroll
        for (int j = 0; j < 4; j++) {
            int r = r8 + j * 32;
            cp_async16(sA + r * P1 + c8 * 8, gA + (size_t)r * HIDDEN + kc + c8 * 8);
        }
#pragma unroll
        for (int j = 0; j < 2; j++) {
            int r = r8 + j * 32;
            cp_async16(sBg + r * P1 + c8 * 8, gBg + (size_t)r * HIDDEN + kc + c8 * 8);
            cp_async16(sBu + r * P1 + c8 * 8, gBu + (size_t)r * HIDDEN + kc + c8 * 8);
        }
        cp_commit();
    };

    const int NK = HIDDEN / 64;  // 64
    prefetch(0, 0);
    prefetch(1, 1);

    for (int kt = 0; kt < NK; kt++) {
        const int s = kt % 3;
        cp_wait1();
        __syncthreads();
        if (kt + 2 < NK) prefetch(kt + 2, (kt + 2) % 3);

        const __half* sA  = sm + s * S1_H;
        const __half* sBg = sA + 128 * P1;
        const __half* sBu = sBg + 64 * P1;

#pragma unroll
        for (int ks = 0; ks < 64; ks += 16) {
            wmma::fragment<wmma::matrix_a, 16, 16, 16, __half, wmma::row_major> af[2];
#pragma unroll
            for (int mt = 0; mt < 2; mt++)
                wmma::load_matrix_sync(af[mt], sA + (wm * 32 + mt * 16) * P1 + ks, P1);
#pragma unroll
            for (int nt = 0; nt < 2; nt++) {
                wmma::fragment<wmma::matrix_b, 16, 16, 16, __half, wmma::col_major> bg, bu;
                wmma::load_matrix_sync(bg, sBg + (wn * 32 + nt * 16) * P1 + ks, P1);
                wmma::load_matrix_sync(bu, sBu + (wn * 32 + nt * 16) * P1 + ks, P1);
#pragma unroll
                for (int mt = 0; mt < 2; mt++) {
                    wmma::mma_sync(accg[mt][nt], af[mt], bg, accg[mt][nt]);
                    wmma::mma_sync(accu[mt][nt], af[mt], bu, accu[mt][nt]);
                }
            }
        }
    }

    // ---- fused SwiGLU epilogue via smem staging
    __syncthreads();
    float* sG = reinterpret_cast<float*>(sm);        // 128 x 68
    float* sU = sG + 128 * 68;                       // 128 x 68
#pragma unroll
    for (int mt = 0; mt < 2; mt++)
#pragma unroll
        for (int nt = 0; nt < 2; nt++) {
            int r0 = wm * 32 + mt * 16, c0 = wn * 32 + nt * 16;
            wmma::store_matrix_sync(sG + r0 * 68 + c0, accg[mt][nt], 68, wmma::mem_row_major);
            wmma::store_matrix_sync(sU + r0 * 68 + c0, accu[mt][nt], 68, wmma::mem_row_major);
        }
    __syncthreads();

#pragma unroll
    for (int j = 0; j < 8; j++) {
        int idx = tid + j * 256;
        int r = idx >> 4, cc = idx & 15;
        float4 g = *reinterpret_cast<const float4*>(sG + r * 68 + cc * 4);
        float4 u = *reinterpret_cast<const float4*>(sU + r * 68 + cc * 4);
        int c0 = nBase + cc * 4;
        float g0 = g.x * s_gate[c0],     u0 = u.x * s_up[c0];
        float g1 = g.y * s_gate[c0 + 1], u1 = u.y * s_up[c0 + 1];
        float g2 = g.z * s_gate[c0 + 2], u2 = u.z * s_up[c0 + 2];
        float g3 = g.w * s_gate[c0 + 3], u3 = u.w * s_up[c0 + 3];
        float h0 = (g0 / (1.f + __expf(-g0))) * u0 * 0.0625f;
        float h1 = (g1 / (1.f + __expf(-g1))) * u1 * 0.0625f;
        float h2 = (g2 / (1.f + __expf(-g2))) * u2 * 0.0625f;
        float h3 = (g3 / (1.f + __expf(-g3))) * u3 * 0.0625f;
        union { __half h[4]; uint2 v; } O;
        O.h[0] = __float2half(h0); O.h[1] = __float2half(h1);
        O.h[2] = __float2half(h2); O.h[3] = __float2half(h3);
        *reinterpret_cast<uint2*>(&g_h[(size_t)(mBase + r) * INTER + c0]) = O.v;
    }
}

// ---------------- GEMM2: down proj, CTA 128x128, 8 warps 64x32, 3 stages ----
// warp grid 2(M) x 4(N); warp tile 64x32 (mt=4, nt=2). Single accumulator ->
// ~110 regs, occupancy 2 preserved; smem-read per MMA halves vs 32x32.
__global__ __launch_bounds__(256, 2)
void k_gemm_down(const float* __restrict__ s_down, float* __restrict__ out) {
    extern __shared__ __half sm2[];

    const int tid = threadIdx.x;
    const int wid = tid >> 5;
    const int wm  = wid >> 2;          // 0..1 (64-row slabs)
    const int wn  = wid & 3;           // 0..3 (32-col slabs)

    int mTile, nTile;
    tile_map(blockIdx.x, HIDDEN / 128, 16, mTile, nTile);
    const int mBase = mTile * 128;
    const int nBase = nTile * 128;

    wmma::fragment<wmma::accumulator, 16, 16, 16, float> acc[4][2];
#pragma unroll
    for (int i = 0; i < 4; i++)
#pragma unroll
        for (int j = 0; j < 2; j++) wmma::fill_fragment(acc[i][j], 0.0f);

    const __half* gA = g_h  + (size_t)mBase * INTER;
    const __half* gB = g_wd + (size_t)nBase * INTER;

    const int r8 = tid >> 3, c8 = tid & 7;

    auto prefetch = [&](int kt, int s) {
        __half* sA = sm2 + s * S2_H;
        __half* sB = sA + 128 * P1;
        const int kc = kt * 64;
#pragma unroll
        for (int j = 0; j < 4; j++) {
            int r = r8 + j * 32;
            cp_async16(sA + r * P1 + c8 * 8, gA + (size_t)r * INTER + kc + c8 * 8);
            cp_async16(sB + r * P1 + c8 * 8, gB + (size_t)r * INTER + kc + c8 * 8);
        }
        cp_commit();
    };

    const int NK = INTER / 64;   // 172
    prefetch(0, 0);
    prefetch(1, 1);

    for (int kt = 0; kt < NK; kt++) {
        const int s = kt % 3;
        cp_wait1();
        __syncthreads();
        if (kt + 2 < NK) prefetch(kt + 2, (kt + 2) % 3);

        const __half* sA = sm2 + s * S2_H;
        const __half* sB = sA + 128 * P1;

#pragma unroll
        for (int ks = 0; ks < 64; ks += 16) {
            wmma::fragment<wmma::matrix_a, 16, 16, 16, __half, wmma::row_major> af[4];
#pragma unroll
            for (int mt = 0; mt < 4; mt++)
                wmma::load_matrix_sync(af[mt], sA + (wm * 64 + mt * 16) * P1 + ks, P1);
#pragma unroll
            for (int nt = 0; nt < 2; nt++) {
                wmma::fragment<wmma::matrix_b, 16, 16, 16, __half, wmma::col_major> bf;
                wmma::load_matrix_sync(bf, sB + (wn * 32 + nt * 16) * P1 + ks, P1);
#pragma unroll
                for (int mt = 0; mt < 4; mt++)
                    wmma::mma_sync(acc[mt][nt], af[mt], bf, acc[mt][nt]);
            }
        }
    }

    // ---- fused scale epilogue via smem staging (128 x 132 fp32 = 67.6 KB)
    __syncthreads();
    float* sO = reinterpret_cast<float*>(sm2);
#pragma unroll
    for (int mt = 0; mt < 4; mt++)
#pragma unroll
        for (int nt = 0; nt < 2; nt++) {
            int r0 = wm * 64 + mt * 16, c0 = wn * 32 + nt * 16;
            wmma::store_matrix_sync(sO + r0 * 132 + c0, acc[mt][nt], 132, wmma::mem_row_major);
        }
    __syncthreads();

#pragma unroll
    for (int j = 0; j < 16; j++) {          // 128 x 32 float4 groups / 256 thr
        int idx = tid + j * 256;
        int r = idx >> 5, cc = idx & 31;
        float4 v = *reinterpret_cast<const float4*>(sO + r * 132 + cc * 4);
        int c0 = nBase + cc * 4;
        float4 o;
        o.x = v.x * s_down[c0]     * 16.f;
        o.y = v.y * s_down[c0 + 1] * 16.f;
        o.z = v.z * s_down[c0 + 2] * 16.f;
        o.w = v.w * s_down[c0 + 3] * 16.f;
        *reinterpret_cast<float4*>(&out[(size_t)(mBase + r) * HIDDEN + c0]) = o;
    }
}

// ---------------- launch -----------------------------------------------------
// Inputs by element count (dict order, x first). Weights are int32 (upcast int8).
extern "C" void kernel_launch(void* const* d_in, const int* in_sizes, int n_in,
                              void* d_out, int out_size) {
    int ix = -1, isd = -1;
    int is_[2]; int ns = 0;
    int iw_[3]; int nw = 0;
    for (int i = 0; i < n_in; i++) {
        int sz = in_sizes[i];
        if (sz == MTOT * HIDDEN)       ix = i;
        else if (sz == HIDDEN)         isd = i;
        else if (sz == INTER)          { if (ns < 2) is_[ns++] = i; }
        else if (sz == INTER * HIDDEN) { if (nw < 3) iw_[nw++] = i; }
    }
    bool dict_order = (ix == 0);
    int iwg = dict_order ? iw_[0] : iw_[1];
    int iwu = dict_order ? iw_[1] : iw_[2];
    int iwd = dict_order ? iw_[2] : iw_[0];

    const float* x  = (const float*)d_in[ix];
    const int*   wg = (const int*)  d_in[iwg];
    const float* sg = (const float*)d_in[is_[0]];
    const int*   wu = (const int*)  d_in[iwu];
    const float* su = (const float*)d_in[is_[1]];
    const int*   wd = (const int*)  d_in[iwd];
    const float* sd = (const float*)d_in[isd];
    float* out = (float*)d_out;

    void *pwg, *pwu, *pwd, *px;
    cudaGetSymbolAddress(&pwg, g_wg);
    cudaGetSymbolAddress(&pwu, g_wu);
    cudaGetSymbolAddress(&pwd, g_wd);
    cudaGetSymbolAddress(&px,  g_x);

    static bool attr_done = false;
    if (!attr_done) {
        cudaFuncSetAttribute(k_gemm_swiglu, cudaFuncAttributeMaxDynamicSharedMemorySize, G1_SMEM);
        cudaFuncSetAttribute(k_gemm_down,   cudaFuncAttributeMaxDynamicSharedMemorySize, G2_SMEM);
        attr_done = true;
    }

    const int nW8 = (INTER * HIDDEN) / 8;
    const int nX8 = (MTOT * HIDDEN) / 8;
    k_i32_to_h<<<(nW8 + 255) / 256, 256>>>(wg, (__half*)pwg, nW8);
    k_i32_to_h<<<(nW8 + 255) / 256, 256>>>(wu, (__half*)pwu, nW8);
    k_i32_to_h<<<(nW8 + 255) / 256, 256>>>(wd, (__half*)pwd, nW8);
    k_f32_to_h<<<(nX8 + 255) / 256, 256>>>(x, (__half*)px, nX8);

    k_gemm_swiglu<<<(MTOT / 128) * (INTER / 64), 256, G1_SMEM>>>(sg, su);
    k_gemm_down  <<<(MTOT / 128) * (HIDDEN / 128), 256, G2_SMEM>>>(sd, out);
}